// round 16
// baseline (speedup 1.0000x reference)
#include <cuda_runtime.h>
#include <cuda_bf16.h>

#define SS 7
#define NCH 25
#define MAXCELLS 8192
#define LAMBDA_COORD 5.0f
#define LAMBDA_NOOBJ 0.5f
#define EPS_SQRT 1e-6f
#define EPS_IOU 1e-10f
#define TPB 512
#define NWARP (TPB / 32)
#define MAXBLK 64

// __device__ globals (zero-init; kernel self-resets -> identical on every replay)
__device__ double g_part[MAXBLK];
__device__ int    g_cnt   = 0;
__device__ int    g_done1 = 0;
__device__ int    g_done2 = 0;
// compacted object-target boxes: corners packed as float4 (area recomputed)
__device__ float4 g_tbox[MAXCELLS];

__global__ void __launch_bounds__(TPB)
k_yolo_v16(const float* __restrict__ pred,
           const float* __restrict__ targ,
           float* __restrict__ out,
           int M, int nblocks, float invB) {
    const int tid  = threadIdx.x;
    const int lane = tid & 31;
    const int wid  = tid >> 5;
    const int i    = blockIdx.x * TPB + tid;   // owned cell

    __shared__ int   s_wbase[NWARP];
    __shared__ int   s_cnt, s_gbase;
    __shared__ float swred[NWARP];
    __shared__ volatile int s_go;
    if (tid == 0) { s_cnt = 0; s_go = 0; }
    __syncthreads();

    // ---------------- Phase 1a: conf-only loss + target compaction ----------
    float local = 0.0f;
    bool isObj = false;
    float pc = 0.0f;

    const float* pp = pred + (size_t)i * NCH;
    const float* tt = targ + (size_t)i * NCH;
    if (i < M) {
        float t4 = __ldg(&tt[4]);     // two independent loads, one latency
        pc = __ldg(&pp[4]);
        isObj = (t4 > 0.0f);
        if (!isObj) local = LAMBDA_NOOBJ * pc * pc;
    }

    // warp -> block -> one global atomic for compaction offsets
    unsigned m = __ballot_sync(0xffffffffu, isObj);
    int nobj = __popc(m);
    if (lane == 0) s_wbase[wid] = (nobj > 0) ? atomicAdd(&s_cnt, nobj) : 0;
    __syncthreads();
    if (tid == 0) s_gbase = (s_cnt > 0) ? atomicAdd(&g_cnt, s_cnt) : 0;
    __syncthreads();
    float t0=0.f, t1=0.f, t2=0.f, t3=0.f;
    if (isObj) {
        int pos = s_gbase + s_wbase[wid] + __popc(m & ((1u << lane) - 1));
        t0 = tt[0]; t1 = tt[1]; t2 = tt[2]; t3 = tt[3];   // same sector as t4
        g_tbox[pos] = make_float4(t0 - t2*0.5f, t1 - t3*0.5f,
                                  t0 + t2*0.5f, t1 + t3*0.5f);
    }

    // ---------------- Arrive at grid barrier (do NOT wait yet) --------------
    __threadfence();
    __syncthreads();
    if (tid == 0) atomicAdd(&g_done1, 1);

    // ---------------- Overlap: obj coord+class losses + pred box ------------
    // These DRAM loads (class channels = fresh sectors) overlap the barrier spin.
    float px1=0.f, py1=0.f, px2=0.f, py2=0.f, pa=0.f;
    if (isObj) {
        float p0 = pp[0], p1 = pp[1], p2 = pp[2], p3 = pp[3];  // same sector as p4
        float dx = p0 - t0;
        float dy = p1 - t1;
        float sw = sqrtf(p2 + EPS_SQRT) - sqrtf(t2 + EPS_SQRT);
        float sh = sqrtf(p3 + EPS_SQRT) - sqrtf(t3 + EPS_SQRT);
        float cl = 0.0f;
        #pragma unroll
        for (int c = 5; c < NCH; c++) {
            float d = pp[c] - tt[c];
            cl += d * d;
        }
        local = LAMBDA_COORD * (dx*dx + dy*dy + sw*sw + sh*sh) + cl;
        px1 = p0 - p2*0.5f;  py1 = p1 - p3*0.5f;
        px2 = p0 + p2*0.5f;  py2 = p1 + p3*0.5f;
        pa  = (px2 - px1) * (py2 - py1);
    }

    // ---------------- Now wait for all blocks --------------------------------
    if (tid == 0) {
        volatile int* vd = &g_done1;
        while (*vd < nblocks) { }
        s_go = 1;
    }
    // all threads wait on the shared flag via syncthreads after tid0 sets it
    __syncthreads();
    __threadfence();

    const int K = g_cnt;

    // ---------------- Phase 2: owning warp computes conf loss ---------------
    unsigned obj_mask = __ballot_sync(0xffffffffu, isObj);
    while (obj_mask) {
        int src = __ffs(obj_mask) - 1;
        obj_mask &= obj_mask - 1;
        float bx1 = __shfl_sync(0xffffffffu, px1, src);
        float by1 = __shfl_sync(0xffffffffu, py1, src);
        float bx2 = __shfl_sync(0xffffffffu, px2, src);
        float by2 = __shfl_sync(0xffffffffu, py2, src);
        float ba  = __shfl_sync(0xffffffffu, pa,  src);
        float best = -1.0f;
        for (int j = lane; j < K; j += 32) {
            float4 tb = g_tbox[j];
            float iw = fminf(bx2, tb.z) - fmaxf(bx1, tb.x);
            float ih = fminf(by2, tb.w) - fmaxf(by1, tb.y);
            iw = fmaxf(iw, 0.0f);
            ih = fmaxf(ih, 0.0f);
            float inter = iw * ih;
            float tarea = (tb.z - tb.x) * (tb.w - tb.y);
            float iou = __fdividef(inter, ba + tarea - inter + EPS_IOU);
            best = fmaxf(best, iou);
        }
        #pragma unroll
        for (int off = 16; off > 0; off >>= 1)
            best = fmaxf(best, __shfl_xor_sync(0xffffffffu, best, off));
        if (lane == src) {
            float d = pc - best;
            local += d * d;
        }
    }

    // ---------------- Single merged block reduction (float) -----------------
    #pragma unroll
    for (int off = 16; off > 0; off >>= 1)
        local += __shfl_down_sync(0xffffffffu, local, off);
    if (lane == 0) swred[wid] = local;
    __syncthreads();
    if (wid == 0) {
        float v = (lane < NWARP) ? swred[lane] : 0.0f;
        #pragma unroll
        for (int off = 8; off > 0; off >>= 1)
            v += __shfl_down_sync(0xffffffffu, v, off);
        if (lane == 0) g_part[blockIdx.x] = (double)v;
    }

    // ---------------- Last block finalizes + resets --------------------------
    __threadfence();
    __syncthreads();
    __shared__ int is_last;
    if (tid == 0) is_last = (atomicAdd(&g_done2, 1) == nblocks - 1) ? 1 : 0;
    __syncthreads();
    if (!is_last) return;

    if (tid == 0) {
        double tot = 0.0;
        for (int b = 0; b < nblocks; b++) tot += g_part[b];
        out[0] = (float)(tot * (double)invB);
        g_cnt   = 0;   // reset for next graph replay
        g_done1 = 0;
        g_done2 = 0;
    }
}

extern "C" void kernel_launch(void* const* d_in, const int* in_sizes, int n_in,
                              void* d_out, int out_size) {
    const float* pred = (const float*)d_in[0];
    const float* targ = (const float*)d_in[1];
    float* out = (float*)d_out;

    int total = in_sizes[0];           // B * S * S * N
    int M = total / NCH;               // 6272 cells
    int B = M / (SS * SS);
    float invB = 1.0f / (float)B;

    int nblocks = (M + TPB - 1) / TPB; // 13  (co-resident: 13 << #SMs)
    k_yolo_v16<<<nblocks, TPB>>>(pred, targ, out, M, nblocks, invB);
}

// round 17
// speedup vs baseline: 1.1336x; 1.1336x over previous
#include <cuda_runtime.h>
#include <cuda_bf16.h>

#define SS 7
#define NCH 25
#define MAXCELLS 8192
#define LAMBDA_COORD 5.0f
#define LAMBDA_NOOBJ 0.5f
#define EPS_SQRT 1e-6f
#define EPS_IOU 1e-10f
#define TPB 512
#define NWARP (TPB / 32)
#define MAXBLK 64

// __device__ globals (zero-init; kernel self-resets -> identical on every replay)
__device__ double g_part[MAXBLK];
__device__ int    g_cnt   = 0;
__device__ int    g_done1 = 0;
__device__ int    g_done2 = 0;
// compacted object-target boxes: corners packed as float4 (area recomputed)
__device__ float4 g_tbox[MAXCELLS];

__global__ void __launch_bounds__(TPB)
k_yolo_v17(const float* __restrict__ pred,
           const float* __restrict__ targ,
           float* __restrict__ out,
           int M, int nblocks, float invB) {
    const int tid  = threadIdx.x;
    const int lane = tid & 31;
    const int wid  = tid >> 5;
    const int i    = blockIdx.x * TPB + tid;   // owned cell

    __shared__ float swred[NWARP];

    // ---------------- Phase 1a: conf-only loss + target compaction ----------
    float local = 0.0f;
    bool isObj = false;
    float pc = 0.0f;

    const float* pp = pred + (size_t)i * NCH;
    const float* tt = targ + (size_t)i * NCH;
    if (i < M) {
        float t4 = __ldg(&tt[4]);     // two independent loads, one latency
        pc = __ldg(&pp[4]);
        isObj = (t4 > 0.0f);
        if (!isObj) local = LAMBDA_NOOBJ * pc * pc;
    }

    // Direct per-warp global compaction: one L2 atomic per warp with obj lanes.
    // No block-level aggregation, no pre-barrier __syncthreads rounds.
    unsigned m = __ballot_sync(0xffffffffu, isObj);
    int nobj = __popc(m);
    int wbase = 0;
    if (nobj > 0) {
        if (lane == __ffs(m) - 1) wbase = atomicAdd(&g_cnt, nobj);
        wbase = __shfl_sync(0xffffffffu, wbase, __ffs(m) - 1);
    }
    float t0=0.f, t1=0.f, t2=0.f, t3=0.f;
    if (isObj) {
        int pos = wbase + __popc(m & ((1u << lane) - 1));
        t0 = tt[0]; t1 = tt[1]; t2 = tt[2]; t3 = tt[3];   // same sector as t4
        g_tbox[pos] = make_float4(t0 - t2*0.5f, t1 - t3*0.5f,
                                  t0 + t2*0.5f, t1 + t3*0.5f);
    }

    // ---------------- Arrive at grid barrier (do NOT wait yet) --------------
    __threadfence();
    __syncthreads();                  // all g_tbox stores + atomics issued
    if (tid == 0) atomicAdd(&g_done1, 1);

    // ---------------- Overlap: obj coord+class losses + pred box ------------
    // Class-channel DRAM loads (fresh sectors) overlap the barrier spin.
    float px1=0.f, py1=0.f, px2=0.f, py2=0.f, pa=0.f;
    if (isObj) {
        float p0 = pp[0], p1 = pp[1], p2 = pp[2], p3 = pp[3];  // same sector as p4
        float dx = p0 - t0;
        float dy = p1 - t1;
        float sw = sqrtf(p2 + EPS_SQRT) - sqrtf(t2 + EPS_SQRT);
        float sh = sqrtf(p3 + EPS_SQRT) - sqrtf(t3 + EPS_SQRT);
        float cl = 0.0f;
        #pragma unroll
        for (int c = 5; c < NCH; c++) {
            float d = pp[c] - tt[c];
            cl += d * d;
        }
        local = LAMBDA_COORD * (dx*dx + dy*dy + sw*sw + sh*sh) + cl;
        px1 = p0 - p2*0.5f;  py1 = p1 - p3*0.5f;
        px2 = p0 + p2*0.5f;  py2 = p1 + p3*0.5f;
        pa  = (px2 - px1) * (py2 - py1);
    }

    // ---------------- Now wait for all blocks --------------------------------
    if (tid == 0) {
        volatile int* vd = &g_done1;
        while (*vd < nblocks) { }
    }
    __syncthreads();
    __threadfence();

    const int K = g_cnt;

    // ---------------- Phase 2: owning warp computes conf loss ---------------
    unsigned obj_mask = __ballot_sync(0xffffffffu, isObj);
    while (obj_mask) {
        int src = __ffs(obj_mask) - 1;
        obj_mask &= obj_mask - 1;
        float bx1 = __shfl_sync(0xffffffffu, px1, src);
        float by1 = __shfl_sync(0xffffffffu, py1, src);
        float bx2 = __shfl_sync(0xffffffffu, px2, src);
        float by2 = __shfl_sync(0xffffffffu, py2, src);
        float ba  = __shfl_sync(0xffffffffu, pa,  src);
        float best = -1.0f;
        for (int j = lane; j < K; j += 32) {
            float4 tb = g_tbox[j];
            float iw = fminf(bx2, tb.z) - fmaxf(bx1, tb.x);
            float ih = fminf(by2, tb.w) - fmaxf(by1, tb.y);
            iw = fmaxf(iw, 0.0f);
            ih = fmaxf(ih, 0.0f);
            float inter = iw * ih;
            float tarea = (tb.z - tb.x) * (tb.w - tb.y);
            float iou = __fdividef(inter, ba + tarea - inter + EPS_IOU);
            best = fmaxf(best, iou);
        }
        #pragma unroll
        for (int off = 16; off > 0; off >>= 1)
            best = fmaxf(best, __shfl_xor_sync(0xffffffffu, best, off));
        if (lane == src) {
            float d = pc - best;
            local += d * d;
        }
    }

    // ---------------- Single merged block reduction (float) -----------------
    #pragma unroll
    for (int off = 16; off > 0; off >>= 1)
        local += __shfl_down_sync(0xffffffffu, local, off);
    if (lane == 0) swred[wid] = local;
    __syncthreads();
    if (wid == 0) {
        float v = (lane < NWARP) ? swred[lane] : 0.0f;
        #pragma unroll
        for (int off = 8; off > 0; off >>= 1)
            v += __shfl_down_sync(0xffffffffu, v, off);
        if (lane == 0) g_part[blockIdx.x] = (double)v;
    }

    // ---------------- Last block finalizes + resets --------------------------
    __threadfence();
    __syncthreads();
    __shared__ int is_last;
    if (tid == 0) is_last = (atomicAdd(&g_done2, 1) == nblocks - 1) ? 1 : 0;
    __syncthreads();
    if (!is_last) return;

    if (tid == 0) {
        double tot = 0.0;
        for (int b = 0; b < nblocks; b++) tot += g_part[b];
        out[0] = (float)(tot * (double)invB);
        g_cnt   = 0;   // reset for next graph replay
        g_done1 = 0;
        g_done2 = 0;
    }
}

extern "C" void kernel_launch(void* const* d_in, const int* in_sizes, int n_in,
                              void* d_out, int out_size) {
    const float* pred = (const float*)d_in[0];
    const float* targ = (const float*)d_in[1];
    float* out = (float*)d_out;

    int total = in_sizes[0];           // B * S * S * N
    int M = total / NCH;               // 6272 cells
    int B = M / (SS * SS);
    float invB = 1.0f / (float)B;

    int nblocks = (M + TPB - 1) / TPB; // 13  (co-resident: 13 << #SMs)
    k_yolo_v17<<<nblocks, TPB>>>(pred, targ, out, M, nblocks, invB);
}